// round 1
// baseline (speedup 1.0000x reference)
#include <cuda_runtime.h>

// ---------------------------------------------------------------------------
// Tri-plane sampling:
//   p = (pts - 1.6) * (-0.625) - 1
//   9 grids: level l in {0,1,2} (R = 128,256,512), plane p in {0,1,2}
//   plane 0 samples (p.y -> W, p.z -> H), plane 1 (p.x, p.z), plane 2 (p.x, p.y)
//   bilinear sample 32 channels each, concat -> out[N, 288]
//
// Strategy: transpose every grid [32,R,R] -> [R*R,32] into a static device
// buffer (coalesced 128B gathers per corner), then warp-per-point sampling
// with lane = channel.
// ---------------------------------------------------------------------------

// pixel offsets (in pixels) of each of the 9 transposed grids
//   l0: 128^2=16384 px/plane, l1: 256^2=65536, l2: 512^2=262144
#define TOTAL_PX 1032192u   // 3*16384 + 3*65536 + 3*262144
__device__ float g_tp[TOTAL_PX * 32];  // 132.1 MB scratch

__global__ void transpose_grid(const float* __restrict__ g, int npix,
                               unsigned dst_px_off) {
    // g: [32, npix] -> g_tp[dst_px_off .. ][npix, 32]
    __shared__ float tile[32][33];
    const int pix0 = blockIdx.x * 32;
    const int tx = threadIdx.x;   // 0..31
    const int ty = threadIdx.y;   // 0..7

    #pragma unroll
    for (int c = ty; c < 32; c += 8) {
        // coalesced read along pixel dim for channel c
        tile[tx][c] = __ldg(g + (size_t)c * npix + pix0 + tx);
    }
    __syncthreads();

    float* dst = g_tp + (size_t)dst_px_off * 32;
    #pragma unroll
    for (int r = ty; r < 32; r += 8) {
        // coalesced write: 32 consecutive channels of pixel (pix0 + r)
        dst[(size_t)(pix0 + r) * 32 + tx] = tile[r][tx];
    }
}

__global__ void __launch_bounds__(256)
sample_kernel(const float* __restrict__ pts, float* __restrict__ out, int n) {
    const int gw   = (int)((blockIdx.x * (unsigned)blockDim.x + threadIdx.x) >> 5);
    const int lane = threadIdx.x & 31;
    if (gw >= n) return;

    // broadcast loads (all lanes same address -> 1 transaction each)
    const float vx = __ldg(pts + 3 * (size_t)gw + 0);
    const float vy = __ldg(pts + 3 * (size_t)gw + 1);
    const float vz = __ldg(pts + 3 * (size_t)gw + 2);

    // p = (v - BOUNDS) * (2 / (-2*BOUNDS)) - 1, BOUNDS = 1.6
    const float px = (vx - 1.6f) * (-0.625f) - 1.0f;
    const float py = (vy - 1.6f) * (-0.625f) - 1.0f;
    const float pz = (vz - 1.6f) * (-0.625f) - 1.0f;

    // plane -> (W coord, H coord)
    const float cw[3] = {py, px, px};
    const float ch[3] = {pz, pz, py};

    const int Rs[3] = {128, 256, 512};
    const unsigned base_px[9] = {0u,      16384u,  32768u,
                                 49152u,  114688u, 180224u,
                                 245760u, 507904u, 770048u};

    float* outp = out + (size_t)gw * 288 + lane;

    #pragma unroll
    for (int l = 0; l < 3; l++) {
        const int   R   = Rs[l];
        const float Rm1 = (float)(R - 1);
        #pragma unroll
        for (int p = 0; p < 3; p++) {
            // match reference op order: ((c + 1) * 0.5) * (W-1), then clip
            float x = (cw[p] + 1.0f) * 0.5f * Rm1;
            x = fminf(fmaxf(x, 0.0f), Rm1);
            float y = (ch[p] + 1.0f) * 0.5f * Rm1;
            y = fminf(fmaxf(y, 0.0f), Rm1);

            const float x0f = floorf(x), y0f = floorf(y);
            const float wx = x - x0f,    wy = y - y0f;
            const int x0 = (int)x0f,     y0 = (int)y0f;
            const int x1 = min(x0 + 1, R - 1);
            const int y1 = min(y0 + 1, R - 1);

            const float* base = g_tp + (size_t)base_px[l * 3 + p] * 32;
            // each load: 32 lanes x 4B consecutive = one 128B transaction
            const float v00 = __ldg(base + (((size_t)y0 * R + x0) << 5) + lane);
            const float v01 = __ldg(base + (((size_t)y0 * R + x1) << 5) + lane);
            const float v10 = __ldg(base + (((size_t)y1 * R + x0) << 5) + lane);
            const float v11 = __ldg(base + (((size_t)y1 * R + x1) << 5) + lane);

            const float r = (v00 * (1.0f - wx) + v01 * wx) * (1.0f - wy)
                          + (v10 * (1.0f - wx) + v11 * wx) * wy;

            outp[(l * 3 + p) * 32] = r;  // coalesced 128B store
        }
    }
}

extern "C" void kernel_launch(void* const* d_in, const int* in_sizes, int n_in,
                              void* d_out, int out_size) {
    const float* pts = (const float*)d_in[0];
    const int n = in_sizes[0] / 3;  // 300000 points

    static const unsigned base_px[9] = {0u,      16384u,  32768u,
                                        49152u,  114688u, 180224u,
                                        245760u, 507904u, 770048u};
    static const int npix[9] = {16384, 16384, 16384,
                                65536, 65536, 65536,
                                262144, 262144, 262144};

    // 1) transpose all 9 grids [32,R,R] -> [R*R,32]
    dim3 tthreads(32, 8);
    for (int i = 0; i < 9; i++) {
        transpose_grid<<<npix[i] / 32, tthreads>>>(
            (const float*)d_in[1 + i], npix[i], base_px[i]);
    }

    // 2) warp-per-point sampling (8 warps / 256-thread block)
    const int blocks = (n + 7) / 8;
    sample_kernel<<<blocks, 256>>>(pts, (float*)d_out, n);
}